// round 15
// baseline (speedup 1.0000x reference)
#include <cuda_runtime.h>
#include <cuda_fp16.h>
#include <cstdint>

#define TT   2048
#define DIMK 1024
#define HIDN 128

typedef unsigned long long u64;
typedef unsigned int u32;

// ---------------- scratch (__device__ globals; no runtime alloc) ------------
__device__ __half g_ewh[TT * TT];        // exp(w) fp16 [t][s]
__device__ __half g_zs[TT * TT];         // zT fp16 [col][s]
__device__ __half g_wh[256 * DIMK];      // W^T interleaved fp16 [n][k]

// ---------------- helpers ----------------------------------------------------
__device__ __forceinline__ u32 smem_u32(const void* p) {
    u32 a;
    asm("{ .reg .u64 t; cvta.to.shared.u64 t, %1; cvt.u32.u64 %0, t; }"
        : "=r"(a) : "l"(p));
    return a;
}
__device__ __forceinline__ void cp16(u32 s, const void* g) {
    asm volatile("cp.async.cg.shared.global [%0], [%1], 16;" :: "r"(s), "l"(g));
}
#define CP_COMMIT() asm volatile("cp.async.commit_group;" ::: "memory")
#define CP_WAIT2()  asm volatile("cp.async.wait_group 2;" ::: "memory")

__device__ __forceinline__ void ldsm4(u32 addr, u32& r0, u32& r1, u32& r2, u32& r3) {
    asm volatile("ldmatrix.sync.aligned.m8n8.x4.shared.b16 {%0,%1,%2,%3}, [%4];"
                 : "=r"(r0), "=r"(r1), "=r"(r2), "=r"(r3) : "r"(addr));
}
__device__ __forceinline__ void mma16816(float* d, u32 a0, u32 a1, u32 a2, u32 a3,
                                         u32 b0, u32 b1) {
    asm volatile(
        "mma.sync.aligned.m16n8k16.row.col.f32.f16.f16.f32 "
        "{%0,%1,%2,%3}, {%4,%5,%6,%7}, {%8,%9}, {%0,%1,%2,%3};"
        : "+f"(d[0]), "+f"(d[1]), "+f"(d[2]), "+f"(d[3])
        : "r"(a0), "r"(a1), "r"(a2), "r"(a3), "r"(b0), "r"(b1));
}
__device__ __forceinline__ u32 f2h2(float a, float b) {
    __half2 h = __floats2half2_rn(a, b);
    return *(u32*)&h;
}

// ---------------- smem layout: XOR-swizzled, ROWB=64, 4 stages ---------------
// addr(row, col16) = row*64 + ((col16 ^ (row & 3)) * 16),  col16 in [0,4)
#define MAT_B  (128 * 64)            // 8192 per operand
#define OFF_A  0
#define OFF_B  MAT_B
#define STAGEB (2 * MAT_B)           // 16384
#define NSTG   4
#define SMEMTOT (NSTG * STAGEB)      // 65536 -> 2 CTAs/SM

__device__ __forceinline__ u32 sw_off(int row, int col16) {
    return (u32)(row * 64) + (u32)((col16 ^ (row & 3)) << 4);
}

// 512-thread cp.async loader (A fp16 + B fp16), used by mainTC.
__device__ __forceinline__ void load_stage(
    u32 dst,
    const char* pA, size_t sA, int m0,
    const char* pB, size_t sB, int n0,
    int chunk, int tid) {
    const size_t cb = (size_t)chunk * 64;
    const int rr = tid >> 2, ko = tid & 3;
    const u32 so = sw_off(rr, ko);
    cp16(dst + OFF_A + so,
         pA + (size_t)(m0 + rr) * sA + cb + (size_t)ko * 16);
    cp16(dst + OFF_B + so,
         pB + (size_t)(n0 + rr) * sB + cb + (size_t)ko * 16);
}

// one k=16 phase: warp tile 32x32 -> 2 A-ldsm, 2 B-ldsm, 8 MMA (swizzled)
__device__ __forceinline__ void phase(u32 s0,
                                      u32 aBase, u32 aSw, u32 aCol,
                                      u32 bBase, u32 bSw, u32 bCol,
                                      int ks, float (&acc)[2][4][4]) {
    const u32 acsw = (u32)(((u32)(ks * 2) + aCol) ^ aSw) << 4;
    const u32 bcsw = (u32)(((u32)(ks * 2) + bCol) ^ bSw) << 4;
    u32 Af[2][4], Bf[2][4];
#pragma unroll
    for (int mt = 0; mt < 2; mt++)
        ldsm4(s0 + OFF_A + aBase + (u32)mt * 1024 + acsw,
              Af[mt][0], Af[mt][1], Af[mt][2], Af[mt][3]);
#pragma unroll
    for (int np = 0; np < 2; np++)
        ldsm4(s0 + OFF_B + bBase + (u32)np * 1024 + bcsw,
              Bf[np][0], Bf[np][1], Bf[np][2], Bf[np][3]);
#pragma unroll
    for (int mt = 0; mt < 2; mt++)
#pragma unroll
        for (int nt = 0; nt < 4; nt++)
            mma16816(acc[mt][nt], Af[mt][0], Af[mt][1], Af[mt][2], Af[mt][3],
                     Bf[nt >> 1][(nt & 1) * 2], Bf[nt >> 1][(nt & 1) * 2 + 1]);
}

// ---------------- prep kernel: W^T interleave + fp16 ------------------------
__global__ void k_wt(const float* __restrict__ wk, const float* __restrict__ wv) {
    __shared__ float tK[32][33], tV[32][33];
    const int bs = blockIdx.x << 5;
    const int bh = blockIdx.y << 5;
    const int tx = threadIdx.x, ty = threadIdx.y;
#pragma unroll
    for (int i = 0; i < 32; i += 8) {
        tK[ty + i][tx] = wk[(bs + ty + i) * HIDN + bh + tx];
        tV[ty + i][tx] = wv[(bs + ty + i) * HIDN + bh + tx];
    }
    __syncthreads();
#pragma unroll
    for (int i = 0; i < 32; i += 8) {
        int hl = ty + i;
        size_t oK = (size_t)(2 * (bh + hl)) * DIMK + bs + tx;
        g_wh[oK] = __float2half_rn(tK[tx][hl]);
        g_wh[oK + DIMK] = __float2half_rn(tV[tx][hl]);
    }
}

// ---------------- projection GEMM + fused exp(w) + exp/transpose epilogue ---
#define NCH_P (DIMK / 32)   // 32
#define ROWH  136
__global__ __launch_bounds__(512, 2) void k_projTC(
    const float* __restrict__ x, const float* __restrict__ w,
    const float* __restrict__ bk, const float* __restrict__ bv) {
    extern __shared__ char smem[];
    const u32 sb = smem_u32(smem);
    const int tid = threadIdx.x;
    const int wid = tid >> 5, lane = tid & 31;
    const int m0 = blockIdx.x << 7;    // 128 m-blocks
    const int n0 = blockIdx.y << 7;    // 2 n-blocks
    const int warp_m = wid >> 2, warp_n = wid & 3;
    const int m_base = warp_m * 32, n_base = warp_n * 32;

    float acc[2][4][4];
#pragma unroll
    for (int i = 0; i < 2; i++)
#pragma unroll
        for (int j = 0; j < 4; j++)
#pragma unroll
            for (int q = 0; q < 4; q++) acc[i][j][q] = 0.0f;

    // swizzled ldsm lane params
    const int a_row = m_base + (lane & 15);
    const u32 aBase = (u32)a_row * 64, aSw = (u32)(a_row & 3), aCol = (u32)(lane >> 4);
    const int b_row = n_base + (lane & 7) + ((lane >> 4) << 3);
    const u32 bBase = (u32)b_row * 64, bSw = (u32)(b_row & 3), bCol = (u32)((lane >> 3) & 1);

    // A loader state: each thread owns one 16B fp16 chunk per stage
    const int rr = tid >> 2, ko = tid & 3;
    const float* xrow = x + (size_t)(m0 + rr) * DIMK + ko * 8;
    const u32 a_sts = sw_off(rr, ko);

    auto ldgA = [&](int ck) -> uint4 {
        float4 f0 = *(const float4*)(xrow + ck * 32);
        float4 f1 = *(const float4*)(xrow + ck * 32 + 4);
        uint4 r;
        r.x = f2h2(f0.x, f0.y);
        r.y = f2h2(f0.z, f0.w);
        r.z = f2h2(f1.x, f1.y);
        r.w = f2h2(f1.z, f1.w);
        return r;
    };
    auto bload = [&](int ck) {
        cp16(sb + (u32)(ck & 3) * STAGEB + OFF_B + a_sts,
             (const char*)g_wh + (size_t)(n0 + rr) * 2048 + (size_t)ck * 64 + (size_t)ko * 16);
    };

    // prologue: A 0,1 in smem; A 2 held; B 0,1,2 committed
    uint4 hold = ldgA(0);
    *(uint4*)(smem + 0 * STAGEB + OFF_A + a_sts) = hold;
    hold = ldgA(1);
    *(uint4*)(smem + 1 * STAGEB + OFF_A + a_sts) = hold;
    hold = ldgA(2);
    bload(0); CP_COMMIT();
    bload(1); CP_COMMIT();
    bload(2); CP_COMMIT();

    // ---- fused exp(w) -> g_ewh: this CTA's 1/256 slice, overlapping fill ----
    {
        const int cta = blockIdx.x * 2 + blockIdx.y;      // 0..255
        const float4* wsrc = (const float4*)w + (size_t)cta * 4096;
        ushort4* wdst = (ushort4*)g_ewh + (size_t)cta * 4096;
#pragma unroll
        for (int i = 0; i < 8; i++) {
            float4 v = wsrc[tid + 512 * i];
            ushort4 H;
            H.x = __half_as_ushort(__float2half_rn(__expf(v.x)));
            H.y = __half_as_ushort(__float2half_rn(__expf(v.y)));
            H.z = __half_as_ushort(__float2half_rn(__expf(v.z)));
            H.w = __half_as_ushort(__float2half_rn(__expf(v.w)));
            wdst[tid + 512 * i] = H;
        }
    }

    CP_WAIT2();
    __syncthreads();

#pragma unroll 1
    for (int c = 0; c < NCH_P; c++) {
        const u32 s0 = sb + (u32)(c & 3) * STAGEB;
        phase(s0, aBase, aSw, aCol, bBase, bSw, bCol, 0, acc);
        phase(s0, aBase, aSw, aCol, bBase, bSw, bCol, 1, acc);
        if (c + 2 < NCH_P)
            *(uint4*)(smem + (size_t)((c + 2) & 3) * STAGEB + OFF_A + a_sts) = hold;
        if (c + 3 < NCH_P) {
            hold = ldgA(c + 3);
            bload(c + 3);
        }
        CP_COMMIT();
        CP_WAIT2();
        __syncthreads();
    }

    // epilogue: bias + exp, transpose via smem, write g_zs [col][s] fp16
    __half* st = (__half*)smem;
#pragma unroll
    for (int mt = 0; mt < 2; mt++) {
        const int sl = m_base + mt * 16 + (lane >> 2);
#pragma unroll
        for (int nt = 0; nt < 4; nt++) {
            const int nl = n_base + nt * 8 + 2 * (lane & 3);
            const int h = (n0 + nl) >> 1;
            const float bkh = bk[h], bvh = bv[h];
            float ek0 = __expf(acc[mt][nt][0] + bkh);
            float v0 = acc[mt][nt][1] + bvh;
            float ek1 = __expf(acc[mt][nt][2] + bkh);
            float v1 = acc[mt][nt][3] + bvh;
            st[nl * ROWH + sl] = __float2half_rn(ek0 * v0);
            st[(nl + 1) * ROWH + sl] = __float2half_rn(ek0);
            st[nl * ROWH + sl + 8] = __float2half_rn(ek1 * v1);
            st[(nl + 1) * ROWH + sl + 8] = __float2half_rn(ek1);
        }
    }
    __syncthreads();
    const int b = m0 >> 11;
    const int s0g = m0 & 2047;
#pragma unroll
    for (int i = 0; i < 4; i++) {
        int j = tid + 512 * i;         // 0..2047
        int row = j >> 4;              // 0..127
        int ch = j & 15;
        uint4 v = *(const uint4*)((const char*)st + (size_t)row * (ROWH * 2) + ch * 16);
        *(uint4*)((char*)(g_zs + (size_t)(b * 256 + n0 + row) * TT + s0g) + ch * 16) = v;
    }
}

// ---------------- main GEMM (swizzled layout, same schedule) -----------------
#define NCH_M (TT / 32)   // 64
__global__ __launch_bounds__(512, 2) void k_mainTC(float* __restrict__ out) {
    extern __shared__ char smem[];
    const u32 sb = smem_u32(smem);
    const int tid = threadIdx.x;
    const int wid = tid >> 5, lane = tid & 31;
    const int m0 = blockIdx.x << 7;   // 16 t-blocks
    const int n0 = blockIdx.y << 7;   // 16 col-blocks
    const int warp_m = wid >> 2, warp_n = wid & 3;
    const int m_base = warp_m * 32, n_base = warp_n * 32;

    float acc[2][4][4];
#pragma unroll
    for (int i = 0; i < 2; i++)
#pragma unroll
        for (int j = 0; j < 4; j++)
#pragma unroll
            for (int q = 0; q < 4; q++) acc[i][j][q] = 0.0f;

    const int a_row = m_base + (lane & 15);
    const u32 aBase = (u32)a_row * 64, aSw = (u32)(a_row & 3), aCol = (u32)(lane >> 4);
    const int b_row = n_base + (lane & 7) + ((lane >> 4) << 3);
    const u32 bBase = (u32)b_row * 64, bSw = (u32)(b_row & 3), bCol = (u32)((lane >> 3) & 1);

    load_stage(sb + 0 * STAGEB, (const char*)g_ewh, 4096, m0,
               (const char*)g_zs, 4096, n0, 0, tid); CP_COMMIT();
    load_stage(sb + 1 * STAGEB, (const char*)g_ewh, 4096, m0,
               (const char*)g_zs, 4096, n0, 1, tid); CP_COMMIT();
    load_stage(sb + 2 * STAGEB, (const char*)g_ewh, 4096, m0,
               (const char*)g_zs, 4096, n0, 2, tid); CP_COMMIT();
    CP_WAIT2();
    __syncthreads();

#pragma unroll 1
    for (int c = 0; c < NCH_M; c++) {
        const u32 s0 = sb + (u32)(c & 3) * STAGEB;
        phase(s0, aBase, aSw, aCol, bBase, bSw, bCol, 0, acc);
        phase(s0, aBase, aSw, aCol, bBase, bSw, bCol, 1, acc);
        if (c + 3 < NCH_M)
            load_stage(sb + (u32)((c + 3) & 3) * STAGEB,
                       (const char*)g_ewh, 4096, m0,
                       (const char*)g_zs, 4096, n0, c + 3, tid);
        CP_COMMIT();
        CP_WAIT2();
        __syncthreads();
    }

    const int b = n0 >> 8;
#pragma unroll
    for (int mt = 0; mt < 2; mt++) {
        const int t0 = m0 + m_base + mt * 16 + (lane >> 2);
#pragma unroll
        for (int nt = 0; nt < 4; nt++) {
            const int gcol = (n0 & 255) + n_base + nt * 8 + 2 * (lane & 3);
            const int h = gcol >> 1;
            float* o0 = out + ((size_t)(b * TT + t0)) * HIDN + h;
            o0[0] = __fdividef(acc[mt][nt][0], acc[mt][nt][1]);
            o0[8 * HIDN] = __fdividef(acc[mt][nt][2], acc[mt][nt][3]);
        }
    }
}

// ---------------- launch ----------------
extern "C" void kernel_launch(void* const* d_in, const int* in_sizes, int n_in,
                              void* d_out, int out_size) {
    const float* x  = (const float*)d_in[0];
    const float* wk = (const float*)d_in[1];
    const float* bk = (const float*)d_in[2];
    const float* wv = (const float*)d_in[3];
    const float* bv = (const float*)d_in[4];
    const float* w  = (const float*)d_in[5];
    float* out = (float*)d_out;

    cudaFuncSetAttribute(k_mainTC, cudaFuncAttributeMaxDynamicSharedMemorySize, SMEMTOT);
    cudaFuncSetAttribute(k_projTC, cudaFuncAttributeMaxDynamicSharedMemorySize, SMEMTOT);

    k_wt<<<dim3(32, 4), dim3(32, 8)>>>(wk, wv);
    k_projTC<<<dim3(128, 2), 512, SMEMTOT>>>(x, w, bk, bv);
    k_mainTC<<<dim3(16, 16), 512, SMEMTOT>>>(out);
}

// round 16
// speedup vs baseline: 1.2972x; 1.2972x over previous
#include <cuda_runtime.h>
#include <cuda_fp16.h>
#include <cstdint>

#define TT   2048
#define DIMK 1024
#define HIDN 128

typedef unsigned long long u64;
typedef unsigned int u32;

// ---------------- scratch (__device__ globals; no runtime alloc) ------------
__device__ __half g_ewh[TT * TT];        // exp(w) fp16 [t][s]
__device__ __half g_zs[TT * TT];         // zT fp16 [col][s]
__device__ __half g_wh[256 * DIMK];      // W^T interleaved fp16 [n][k]

// ---------------- helpers ----------------------------------------------------
__device__ __forceinline__ u32 smem_u32(const void* p) {
    u32 a;
    asm("{ .reg .u64 t; cvta.to.shared.u64 t, %1; cvt.u32.u64 %0, t; }"
        : "=r"(a) : "l"(p));
    return a;
}
__device__ __forceinline__ void cp16(u32 s, const void* g) {
    asm volatile("cp.async.cg.shared.global [%0], [%1], 16;" :: "r"(s), "l"(g));
}
#define CP_COMMIT() asm volatile("cp.async.commit_group;" ::: "memory")
#define CP_WAIT2()  asm volatile("cp.async.wait_group 2;" ::: "memory")

__device__ __forceinline__ void ldsm4(u32 addr, u32& r0, u32& r1, u32& r2, u32& r3) {
    asm volatile("ldmatrix.sync.aligned.m8n8.x4.shared.b16 {%0,%1,%2,%3}, [%4];"
                 : "=r"(r0), "=r"(r1), "=r"(r2), "=r"(r3) : "r"(addr));
}
__device__ __forceinline__ void mma16816(float* d, u32 a0, u32 a1, u32 a2, u32 a3,
                                         u32 b0, u32 b1) {
    asm volatile(
        "mma.sync.aligned.m16n8k16.row.col.f32.f16.f16.f32 "
        "{%0,%1,%2,%3}, {%4,%5,%6,%7}, {%8,%9}, {%0,%1,%2,%3};"
        : "+f"(d[0]), "+f"(d[1]), "+f"(d[2]), "+f"(d[3])
        : "r"(a0), "r"(a1), "r"(a2), "r"(a3), "r"(b0), "r"(b1));
}
__device__ __forceinline__ u32 f2h2(float a, float b) {
    __half2 h = __floats2half2_rn(a, b);
    return *(u32*)&h;
}

// ---------------- smem layout: CTA 128x128, k-chunk 32, 4 stages (R14) -------
#define ROWB   80
#define MAT_B  (128 * ROWB)          // 10240 per operand
#define OFF_A  0
#define OFF_B  MAT_B
#define STAGEB (2 * MAT_B)           // 20480
#define NSTG   4
#define SMEMTOT (NSTG * STAGEB)      // 81920 -> 2 CTAs/SM

// 512-thread cp.async loader (A fp16 + B fp16), used by mainTC.
__device__ __forceinline__ void load_stage(
    u32 dst,
    const char* pA, size_t sA, int m0,
    const char* pB, size_t sB, int n0,
    int chunk, int tid) {
    const size_t cb = (size_t)chunk * 64;
    const int rr = tid >> 2, ko = tid & 3;
    cp16(dst + OFF_A + (u32)rr * ROWB + (u32)ko * 16,
         pA + (size_t)(m0 + rr) * sA + cb + (size_t)ko * 16);
    cp16(dst + OFF_B + (u32)rr * ROWB + (u32)ko * 16,
         pB + (size_t)(n0 + rr) * sB + cb + (size_t)ko * 16);
}

// one k=16 phase: warp tile 32x32 -> 2 A-ldsm, 2 B-ldsm, 8 MMA
__device__ __forceinline__ void phase(u32 s0, u32 aoff, u32 boff, int ks,
                                      float (&acc)[2][4][4]) {
    const u32 ak = aoff + (u32)ks * 32;
    const u32 bk = boff + (u32)ks * 32;
    u32 Af[2][4], Bf[2][4];
#pragma unroll
    for (int mt = 0; mt < 2; mt++)
        ldsm4(s0 + OFF_A + ak + (u32)mt * (16 * ROWB),
              Af[mt][0], Af[mt][1], Af[mt][2], Af[mt][3]);
#pragma unroll
    for (int np = 0; np < 2; np++)
        ldsm4(s0 + OFF_B + bk + (u32)np * (16 * ROWB),
              Bf[np][0], Bf[np][1], Bf[np][2], Bf[np][3]);
#pragma unroll
    for (int mt = 0; mt < 2; mt++)
#pragma unroll
        for (int nt = 0; nt < 4; nt++)
            mma16816(acc[mt][nt], Af[mt][0], Af[mt][1], Af[mt][2], Af[mt][3],
                     Bf[nt >> 1][(nt & 1) * 2], Bf[nt >> 1][(nt & 1) * 2 + 1]);
}

// ---------------- prep kernel: W^T interleave + fp16 ------------------------
__global__ void k_wt(const float* __restrict__ wk, const float* __restrict__ wv) {
    __shared__ float tK[32][33], tV[32][33];
    const int bs = blockIdx.x << 5;
    const int bh = blockIdx.y << 5;
    const int tx = threadIdx.x, ty = threadIdx.y;
#pragma unroll
    for (int i = 0; i < 32; i += 8) {
        tK[ty + i][tx] = wk[(bs + ty + i) * HIDN + bh + tx];
        tV[ty + i][tx] = wv[(bs + ty + i) * HIDN + bh + tx];
    }
    __syncthreads();
#pragma unroll
    for (int i = 0; i < 32; i += 8) {
        int hl = ty + i;
        size_t oK = (size_t)(2 * (bh + hl)) * DIMK + bs + tx;
        g_wh[oK] = __float2half_rn(tK[tx][hl]);
        g_wh[oK + DIMK] = __float2half_rn(tV[tx][hl]);
    }
}

// ---------------- projection GEMM + fused exp(w) + exp/transpose epilogue ---
#define NCH_P (DIMK / 32)   // 32
#define ROWH  136
__global__ __launch_bounds__(512, 2) void k_projTC(
    const float* __restrict__ x, const float* __restrict__ w,
    const float* __restrict__ bk, const float* __restrict__ bv) {
    extern __shared__ char smem[];
    const u32 sb = smem_u32(smem);
    const int tid = threadIdx.x;
    const int wid = tid >> 5, lane = tid & 31;
    const int m0 = blockIdx.x << 7;    // 128 m-blocks
    const int n0 = blockIdx.y << 7;    // 2 n-blocks
    const int warp_m = wid >> 2, warp_n = wid & 3;
    const int m_base = warp_m * 32, n_base = warp_n * 32;

    float acc[2][4][4];
#pragma unroll
    for (int i = 0; i < 2; i++)
#pragma unroll
        for (int j = 0; j < 4; j++)
#pragma unroll
            for (int q = 0; q < 4; q++) acc[i][j][q] = 0.0f;

    const u32 aoff = (u32)(m_base + (lane & 15)) * ROWB + (u32)(lane >> 4) * 16;
    const u32 boff = (u32)(n_base + (lane & 7) + ((lane >> 4) << 3)) * ROWB +
                     (u32)((lane >> 3) & 1) * 16;

    // A loader state: each thread owns one 16B fp16 chunk per stage
    const int rr = tid >> 2, ko = tid & 3;
    const float* xrow = x + (size_t)(m0 + rr) * DIMK + ko * 8;
    const u32 a_sts = (u32)rr * ROWB + (u32)ko * 16;

    auto ldgA = [&](int ck) -> uint4 {
        float4 f0 = *(const float4*)(xrow + ck * 32);
        float4 f1 = *(const float4*)(xrow + ck * 32 + 4);
        uint4 r;
        r.x = f2h2(f0.x, f0.y);
        r.y = f2h2(f0.z, f0.w);
        r.z = f2h2(f1.x, f1.y);
        r.w = f2h2(f1.z, f1.w);
        return r;
    };
    auto bload = [&](int ck) {
        cp16(sb + (u32)(ck & 3) * STAGEB + OFF_B + a_sts,
             (const char*)g_wh + (size_t)(n0 + rr) * 2048 + (size_t)ck * 64 + (size_t)ko * 16);
    };

    // prologue: A 0,1 in smem; A 2 held; B 0,1,2 committed
    uint4 hold = ldgA(0);
    *(uint4*)(smem + 0 * STAGEB + OFF_A + a_sts) = hold;
    hold = ldgA(1);
    *(uint4*)(smem + 1 * STAGEB + OFF_A + a_sts) = hold;
    hold = ldgA(2);
    bload(0); CP_COMMIT();
    bload(1); CP_COMMIT();
    bload(2); CP_COMMIT();

    // ---- fused exp(w) -> g_ewh: this CTA's 1/256 slice, overlapping fill ----
    {
        const int cta = blockIdx.x * 2 + blockIdx.y;      // 0..255
        const float4* wsrc = (const float4*)w + (size_t)cta * 4096;
        ushort4* wdst = (ushort4*)g_ewh + (size_t)cta * 4096;
#pragma unroll
        for (int i = 0; i < 8; i++) {
            float4 v = wsrc[tid + 512 * i];
            ushort4 H;
            H.x = __half_as_ushort(__float2half_rn(__expf(v.x)));
            H.y = __half_as_ushort(__float2half_rn(__expf(v.y)));
            H.z = __half_as_ushort(__float2half_rn(__expf(v.z)));
            H.w = __half_as_ushort(__float2half_rn(__expf(v.w)));
            wdst[tid + 512 * i] = H;
        }
    }

    CP_WAIT2();
    __syncthreads();

#pragma unroll 1
    for (int c = 0; c < NCH_P; c++) {
        const u32 s0 = sb + (u32)(c & 3) * STAGEB;
        phase(s0, aoff, boff, 0, acc);
        phase(s0, aoff, boff, 1, acc);
        if (c + 2 < NCH_P)
            *(uint4*)(smem + (size_t)((c + 2) & 3) * STAGEB + OFF_A + a_sts) = hold;
        if (c + 3 < NCH_P) {
            hold = ldgA(c + 3);
            bload(c + 3);
        }
        CP_COMMIT();
        CP_WAIT2();
        __syncthreads();
    }

    // epilogue: bias + exp, transpose via smem, write g_zs [col][s] fp16
    __half* st = (__half*)smem;
#pragma unroll
    for (int mt = 0; mt < 2; mt++) {
        const int sl = m_base + mt * 16 + (lane >> 2);
#pragma unroll
        for (int nt = 0; nt < 4; nt++) {
            const int nl = n_base + nt * 8 + 2 * (lane & 3);
            const int h = (n0 + nl) >> 1;
            const float bkh = bk[h], bvh = bv[h];
            float ek0 = __expf(acc[mt][nt][0] + bkh);
            float v0 = acc[mt][nt][1] + bvh;
            float ek1 = __expf(acc[mt][nt][2] + bkh);
            float v1 = acc[mt][nt][3] + bvh;
            st[nl * ROWH + sl] = __float2half_rn(ek0 * v0);
            st[(nl + 1) * ROWH + sl] = __float2half_rn(ek0);
            st[nl * ROWH + sl + 8] = __float2half_rn(ek1 * v1);
            st[(nl + 1) * ROWH + sl + 8] = __float2half_rn(ek1);
        }
    }
    __syncthreads();
    const int b = m0 >> 11;
    const int s0g = m0 & 2047;
#pragma unroll
    for (int i = 0; i < 4; i++) {
        int j = tid + 512 * i;         // 0..2047
        int row = j >> 4;              // 0..127
        int ch = j & 15;
        uint4 v = *(const uint4*)((const char*)st + (size_t)row * (ROWH * 2) + ch * 16);
        *(uint4*)((char*)(g_zs + (size_t)(b * 256 + n0 + row) * TT + s0g) + ch * 16) = v;
    }
}

// ---------------- main GEMM (R14 loop) + smem-staged coalesced epilogue -----
#define NCH_M (TT / 32)   // 64
#define OROW  68          // fp32 output staging row stride (padding: distinct banks)
__global__ __launch_bounds__(512, 2) void k_mainTC(float* __restrict__ out) {
    extern __shared__ char smem[];
    const u32 sb = smem_u32(smem);
    const int tid = threadIdx.x;
    const int wid = tid >> 5, lane = tid & 31;
    const int m0 = blockIdx.x << 7;   // 16 t-blocks
    const int n0 = blockIdx.y << 7;   // 16 col-blocks
    const int warp_m = wid >> 2, warp_n = wid & 3;
    const int m_base = warp_m * 32, n_base = warp_n * 32;

    float acc[2][4][4];
#pragma unroll
    for (int i = 0; i < 2; i++)
#pragma unroll
        for (int j = 0; j < 4; j++)
#pragma unroll
            for (int q = 0; q < 4; q++) acc[i][j][q] = 0.0f;

    const u32 aoff = (u32)(m_base + (lane & 15)) * ROWB + (u32)(lane >> 4) * 16;
    const u32 boff = (u32)(n_base + (lane & 7) + ((lane >> 4) << 3)) * ROWB +
                     (u32)((lane >> 3) & 1) * 16;

    load_stage(sb + 0 * STAGEB, (const char*)g_ewh, 4096, m0,
               (const char*)g_zs, 4096, n0, 0, tid); CP_COMMIT();
    load_stage(sb + 1 * STAGEB, (const char*)g_ewh, 4096, m0,
               (const char*)g_zs, 4096, n0, 1, tid); CP_COMMIT();
    load_stage(sb + 2 * STAGEB, (const char*)g_ewh, 4096, m0,
               (const char*)g_zs, 4096, n0, 2, tid); CP_COMMIT();
    CP_WAIT2();
    __syncthreads();

#pragma unroll 1
    for (int c = 0; c < NCH_M; c++) {
        const u32 s0 = sb + (u32)(c & 3) * STAGEB;
        phase(s0, aoff, boff, 0, acc);
        phase(s0, aoff, boff, 1, acc);
        if (c + 3 < NCH_M)
            load_stage(sb + (u32)((c + 3) & 3) * STAGEB,
                       (const char*)g_ewh, 4096, m0,
                       (const char*)g_zs, 4096, n0, c + 3, tid);
        CP_COMMIT();
        CP_WAIT2();
        __syncthreads();
    }

    // ---- staged epilogue: divide in regs, STS fp32 [128t][64h], STG coalesced
    __syncthreads();
    float* st = (float*)smem;   // 128 * OROW * 4 = 34816 B < SMEMTOT
#pragma unroll
    for (int mt = 0; mt < 2; mt++) {
        const int tl = m_base + mt * 16 + (lane >> 2);
#pragma unroll
        for (int nt = 0; nt < 4; nt++) {
            const int hl = warp_n * 16 + nt * 4 + (lane & 3);
            st[tl * OROW + hl] = __fdividef(acc[mt][nt][0], acc[mt][nt][1]);
            st[(tl + 8) * OROW + hl] = __fdividef(acc[mt][nt][2], acc[mt][nt][3]);
        }
    }
    __syncthreads();
    const int b = n0 >> 8;
    const int h0 = (n0 & 255) >> 1;
#pragma unroll
    for (int i = 0; i < 4; i++) {
        int idx = tid + 512 * i;     // 0..2047
        int row = idx >> 4;          // 0..127
        int ch = idx & 15;           // 16 x 16B chunks = 64 floats
        float4 v = *(const float4*)(st + row * OROW + ch * 4);
        *(float4*)(out + (size_t)(b * TT + m0 + row) * HIDN + h0 + ch * 4) = v;
    }
}

// ---------------- launch ----------------
extern "C" void kernel_launch(void* const* d_in, const int* in_sizes, int n_in,
                              void* d_out, int out_size) {
    const float* x  = (const float*)d_in[0];
    const float* wk = (const float*)d_in[1];
    const float* bk = (const float*)d_in[2];
    const float* wv = (const float*)d_in[3];
    const float* bv = (const float*)d_in[4];
    const float* w  = (const float*)d_in[5];
    float* out = (float*)d_out;

    cudaFuncSetAttribute(k_mainTC, cudaFuncAttributeMaxDynamicSharedMemorySize, SMEMTOT);
    cudaFuncSetAttribute(k_projTC, cudaFuncAttributeMaxDynamicSharedMemorySize, SMEMTOT);

    k_wt<<<dim3(32, 4), dim3(32, 8)>>>(wk, wv);
    k_projTC<<<dim3(128, 2), 512, SMEMTOT>>>(x, w, bk, bv);
    k_mainTC<<<dim3(16, 16), 512, SMEMTOT>>>(out);
}